// round 3
// baseline (speedup 1.0000x reference)
#include <cuda_runtime.h>
#include <cuda_bf16.h>
#include <math_constants.h>

#define NM 1024
#define HH 256
#define WW 256
#define HW (HH * WW)
#define NQ 16            // partial blocks per mask in stats kernel

// Scratch (no cudaMalloc allowed). Partials are fully overwritten every call
// (deterministic), so no init kernel is needed.
__device__ int   g_phi[NQ * NM];
__device__ int   g_plo[NQ * NM];
__device__ int   g_prmin[NQ * NM];
__device__ int   g_prmax[NQ * NM];
__device__ int   g_pcmin[NQ * NM];
__device__ int   g_pcmax[NQ * NM];
__device__ float g_gated[NM];

// ---------------------------------------------------------------------------
// Kernel A: per-mask stats partials. grid = (NM, NQ), 256 threads.
// Each block handles 16 rows of one mask (16 KB). tx = tid&63 owns columns
// [4*tx,4*tx+3]; ty = tid>>6 owns 4 consecutive rows, loaded as 4 independent
// float4s up-front (MLP >= 4).
// ---------------------------------------------------------------------------
__global__ void __launch_bounds__(256) stats_kernel(const float* __restrict__ logits) {
    const int n   = blockIdx.x;
    const int q   = blockIdx.y;
    const int tid = threadIdx.x;
    const int tx  = tid & 63;
    const int ty  = tid >> 6;
    const int col0 = tx * 4;
    const int r0   = q * 16 + ty * 4;

    const float4* __restrict__ base =
        reinterpret_cast<const float4*>(logits + (size_t)n * HW);

    float4 v0 = base[(r0 + 0) * (WW / 4) + tx];
    float4 v1 = base[(r0 + 1) * (WW / 4) + tx];
    float4 v2 = base[(r0 + 2) * (WW / 4) + tx];
    float4 v3 = base[(r0 + 3) * (WW / 4) + tx];

    int hi = 0, lo = 0;
    int rmin = HH, rmax = -1, cmin = WW, cmax = -1;

#define PROC(v, r)                                                             \
    {                                                                          \
        hi += (v.x > 1.f) + (v.y > 1.f) + (v.z > 1.f) + (v.w > 1.f);           \
        lo += (v.x > -1.f) + (v.y > -1.f) + (v.z > -1.f) + (v.w > -1.f);       \
        int m = (v.x > 0.f) | ((v.y > 0.f) << 1) | ((v.z > 0.f) << 2) |        \
                ((v.w > 0.f) << 3);                                            \
        if (m) {                                                               \
            rmin = min(rmin, r);                                               \
            rmax = max(rmax, r);                                               \
            cmin = min(cmin, col0 + (__ffs(m) - 1));                           \
            cmax = max(cmax, col0 + (31 - __clz(m)));                          \
        }                                                                      \
    }

    PROC(v0, r0 + 0)
    PROC(v1, r0 + 1)
    PROC(v2, r0 + 2)
    PROC(v3, r0 + 3)
#undef PROC

    // warp reduce
#pragma unroll
    for (int o = 16; o > 0; o >>= 1) {
        hi   += __shfl_down_sync(0xffffffffu, hi, o);
        lo   += __shfl_down_sync(0xffffffffu, lo, o);
        rmin  = min(rmin, __shfl_down_sync(0xffffffffu, rmin, o));
        rmax  = max(rmax, __shfl_down_sync(0xffffffffu, rmax, o));
        cmin  = min(cmin, __shfl_down_sync(0xffffffffu, cmin, o));
        cmax  = max(cmax, __shfl_down_sync(0xffffffffu, cmax, o));
    }

    __shared__ int s_hi, s_lo, s_rmin, s_rmax, s_cmin, s_cmax;
    if (tid == 0) { s_hi = 0; s_lo = 0; s_rmin = HH; s_rmax = -1; s_cmin = WW; s_cmax = -1; }
    __syncthreads();
    if ((tid & 31) == 0) {
        atomicAdd(&s_hi, hi);
        atomicAdd(&s_lo, lo);
        atomicMin(&s_rmin, rmin);
        atomicMax(&s_rmax, rmax);
        atomicMin(&s_cmin, cmin);
        atomicMax(&s_cmax, cmax);
    }
    __syncthreads();
    if (tid == 0) {
        const int p = q * NM + n;
        g_phi[p]   = s_hi;
        g_plo[p]   = s_lo;
        g_prmin[p] = s_rmin;
        g_prmax[p] = s_rmax;
        g_pcmin[p] = s_cmin;
        g_pcmax[p] = s_cmax;
    }
}

// ---------------------------------------------------------------------------
// Kernel B: single block (1024 threads). Merge partials, build boxes+validity,
// compact valid candidates, bitonic-sort only next-pow2(V), then NMS via
// suppression bitmasks (V<=256 fast path) or iterative fallback.
// ---------------------------------------------------------------------------
__global__ void __launch_bounds__(1024) nms_kernel(const float* __restrict__ iou,
                                                   float* __restrict__ out_keep,
                                                   float* __restrict__ out_boxes,
                                                   int write_extra) {
    __shared__ float4 s_bx[NM];                // boxes in ORIGINAL index order
    __shared__ float  s_sc[NM];                // compacted+sorted scores
    __shared__ int    s_ord[NM];               // compacted+sorted original idx
    __shared__ float  s_area[NM];              // area per sorted candidate
    __shared__ unsigned s_sup[256 * 8];        // suppression bitmask rows (V<=256)
    __shared__ unsigned s_live[8];
    __shared__ unsigned char s_keep[NM];       // fallback path
    __shared__ int s_cnt;

    const int tid = threadIdx.x;

    // ---- merge 16 partials ----
    int hi = 0, lo = 0, rmin = HH, rmax = -1, cmin = WW, cmax = -1;
#pragma unroll
    for (int q = 0; q < NQ; q++) {
        const int p = q * NM + tid;
        hi  += g_phi[p];
        lo  += g_plo[p];
        rmin = min(rmin, g_prmin[p]);
        rmax = max(rmax, g_prmax[p]);
        cmin = min(cmin, g_pcmin[p]);
        cmax = max(cmax, g_pcmax[p]);
    }

    float4 box;
    if (rmax < 0) box = make_float4(0.f, 0.f, 0.f, 0.f);
    else          box = make_float4((float)cmin, (float)rmin, (float)cmax, (float)rmax);
    s_bx[tid] = box;

    const float ip   = iou[tid];
    const float stab = (float)hi / fmaxf((float)lo, 1.0f);
    const bool  valid = (ip > 0.88f) && (stab >= 0.95f);

    if (tid == 0) s_cnt = 0;
    __syncthreads();
    int pos = -1;
    if (valid) pos = atomicAdd(&s_cnt, 1);
    __syncthreads();
    const int V = s_cnt;

    if (pos >= 0) { s_sc[pos] = ip; s_ord[pos] = tid; }

    int Npad = 1;
    while (Npad < V) Npad <<= 1;
    if (Npad < 2) Npad = 2;
    if (tid >= V && tid < Npad) { s_sc[tid] = -CUDART_INF_F; s_ord[tid] = NM; }
    __syncthreads();

    if (V > 0) {
        // ---- bitonic sort over Npad entries (desc score, asc idx tie-break) ----
        for (int k = 2; k <= Npad; k <<= 1) {
            for (int j = k >> 1; j > 0; j >>= 1) {
                if (tid < Npad) {
                    const int ixj = tid ^ j;
                    if (ixj > tid) {
                        float sa = s_sc[tid], sb = s_sc[ixj];
                        int   ia = s_ord[tid], ib = s_ord[ixj];
                        bool dir = ((tid & k) == 0);  // descending segment
                        bool aBb = (sa > sb) || (sa == sb && ia < ib);
                        bool bBa = (sb > sa) || (sb == sa && ib < ia);
                        if (dir ? bBa : aBb) {
                            s_sc[tid] = sb; s_sc[ixj] = sa;
                            s_ord[tid] = ib; s_ord[ixj] = ia;
                        }
                    }
                }
                __syncthreads();
            }
        }

        if (tid < V) {
            float4 b = s_bx[s_ord[tid]];
            s_area[tid] = fmaxf(b.z - b.x, 0.f) * fmaxf(b.w - b.y, 0.f);
        }
        __syncthreads();

        if (V <= 256) {
            // ---- parallel suppression-matrix build ----
            if (tid < V) {
                const float4 bi = s_bx[s_ord[tid]];
                const float  ai = s_area[tid];
                unsigned w[8] = {0, 0, 0, 0, 0, 0, 0, 0};
                for (int j = tid + 1; j < V; j++) {
                    const float4 bj = s_bx[s_ord[j]];
                    float x0 = fmaxf(bi.x, bj.x), y0 = fmaxf(bi.y, bj.y);
                    float x1 = fminf(bi.z, bj.z), y1 = fminf(bi.w, bj.w);
                    float inter = fmaxf(x1 - x0, 0.f) * fmaxf(y1 - y0, 0.f);
                    float v = inter / fmaxf(ai + s_area[j] - inter, 1e-6f);
                    if (v > 0.7f) w[j >> 5] |= 1u << (j & 31);
                }
#pragma unroll
                for (int k = 0; k < 8; k++) s_sup[tid * 8 + k] = w[k];
            }
            __syncthreads();

            // ---- serial greedy resolution over bitmasks ----
            if (tid == 0) {
                unsigned live[8];
#pragma unroll
                for (int k = 0; k < 8; k++) {
                    int rem = V - k * 32;
                    live[k] = (rem >= 32) ? 0xffffffffu
                                          : (rem > 0 ? ((1u << rem) - 1u) : 0u);
                }
                for (int i = 0; i < V; i++) {
                    if ((live[i >> 5] >> (i & 31)) & 1u) {
#pragma unroll
                        for (int k = 0; k < 8; k++) live[k] &= ~s_sup[i * 8 + k];
                    }
                }
#pragma unroll
                for (int k = 0; k < 8; k++) s_live[k] = live[k];
            }
            __syncthreads();
            if (tid < V)
                s_keep[tid] = (s_live[tid >> 5] >> (tid & 31)) & 1u;
        } else {
            // ---- fallback: iterative greedy (rare) ----
            if (tid < Npad) s_keep[tid] = (tid < V) ? 1 : 0;
            __syncthreads();
            float4 mb = make_float4(0, 0, 0, 0);
            float  ma = 0.f;
            if (tid < V) { mb = s_bx[s_ord[tid]]; ma = s_area[tid]; }
            for (int i = 0; i < V; i++) {
                if (tid < V && s_keep[i] && tid > i && s_keep[tid]) {
                    float4 pb = s_bx[s_ord[i]];
                    float x0 = fmaxf(pb.x, mb.x), y0 = fmaxf(pb.y, mb.y);
                    float x1 = fminf(pb.z, mb.z), y1 = fminf(pb.w, mb.w);
                    float inter = fmaxf(x1 - x0, 0.f) * fmaxf(y1 - y0, 0.f);
                    float v = inter / fmaxf(s_area[i] + ma - inter, 1e-6f);
                    if (v > 0.7f) s_keep[tid] = 0;
                }
                __syncthreads();
            }
        }
    }

    // ---- outputs: defaults, then kept overrides (ordered by __syncthreads) ----
    g_gated[tid] = 0.f;
    if (write_extra) {
        out_keep[tid] = 0.f;
        reinterpret_cast<float4*>(out_boxes)[tid] = s_bx[tid];
    }
    __syncthreads();
    if (tid < V && s_keep[tid]) {
        const int oi = s_ord[tid];
        g_gated[oi] = s_sc[tid];
        if (write_extra) out_keep[oi] = 1.f;
    }
}

// ---------------------------------------------------------------------------
// Kernel C: out = sigmoid(logits) * gated[n]. Zero-gated blocks stream zeros.
// grid = (16, NM), 256 threads, 4 coalesced float4 per thread.
// ---------------------------------------------------------------------------
__global__ void __launch_bounds__(256) out_kernel(const float* __restrict__ logits,
                                                  float* __restrict__ out) {
    const int n   = blockIdx.y;
    const int tid = threadIdx.x;
    const size_t base = (size_t)n * HW + (size_t)blockIdx.x * 4096;
    const float4* __restrict__ in4 = reinterpret_cast<const float4*>(logits + base);
    float4* __restrict__ o4 = reinterpret_cast<float4*>(out + base);

    const float g = g_gated[n];
    if (g == 0.f) {
        const float4 z = make_float4(0.f, 0.f, 0.f, 0.f);
#pragma unroll
        for (int k = 0; k < 4; k++) o4[k * 256 + tid] = z;
    } else {
#pragma unroll
        for (int k = 0; k < 4; k++) {
            float4 v = in4[k * 256 + tid];
            float4 r;
            r.x = g / (1.f + __expf(-v.x));
            r.y = g / (1.f + __expf(-v.y));
            r.z = g / (1.f + __expf(-v.z));
            r.w = g / (1.f + __expf(-v.w));
            o4[k * 256 + tid] = r;
        }
    }
}

// ---------------------------------------------------------------------------
extern "C" void kernel_launch(void* const* d_in, const int* in_sizes, int n_in,
                              void* d_out, int out_size) {
    const float* logits = (const float*)d_in[0];
    const float* iou    = (const float*)d_in[1];
    if (n_in >= 2 && in_sizes[0] == NM && in_sizes[1] == NM * HW) {
        logits = (const float*)d_in[1];
        iou    = (const float*)d_in[0];
    }

    float* out = (float*)d_out;
    const long long NHW = (long long)NM * HW;
    int write_extra = (out_size >= NHW + NM + NM * 4) ? 1 : 0;
    float* out_keep  = out + NHW;
    float* out_boxes = out + NHW + NM;

    stats_kernel<<<dim3(NM, NQ), 256>>>(logits);
    nms_kernel<<<1, 1024>>>(iou, out_keep, out_boxes, write_extra);
    out_kernel<<<dim3(16, NM), 256>>>(logits, out);
}

// round 4
// speedup vs baseline: 1.3752x; 1.3752x over previous
#include <cuda_runtime.h>
#include <cuda_bf16.h>
#include <math_constants.h>

#define NM 1024
#define HH 256
#define WW 256
#define HW (HH * WW)
#define NQ 16            // partial blocks per mask in stats kernel

// Scratch (no cudaMalloc allowed). Fully overwritten every call.
__device__ unsigned g_pp[NQ * NM];   // packed bbox: (rmin,255-rmax,cmin,255-cmax); 0xFFFFFFFF = empty
__device__ unsigned g_pk[NQ * NM];   // packed counts: hi<<16 | lo
__device__ float    g_gated[NM];

// ---------------------------------------------------------------------------
// Kernel A: per-mask stats partials. grid = (NM, NQ), 256 threads.
// Block handles 16 rows; tx=tid&63 owns cols [4tx,4tx+3]; ty=tid>>6 owns 4 rows
// loaded as 4 independent float4s (MLP>=4). Fast classify via vmin/vmax:
// fully-below (-1) float4s cost ~9 instr, fully-above (+1) ~13, boundary ~28.
// ---------------------------------------------------------------------------
__global__ void __launch_bounds__(256) stats_kernel(const float* __restrict__ logits) {
    const int n   = blockIdx.x;
    const int q   = blockIdx.y;
    const int tid = threadIdx.x;
    const int tx  = tid & 63;
    const int ty  = tid >> 6;
    const int col0 = tx * 4;
    const int r0   = q * 16 + ty * 4;

    const float4* __restrict__ base =
        reinterpret_cast<const float4*>(logits + (size_t)n * HW) + tx;

    float4 v0 = base[(size_t)(r0 + 0) * (WW / 4)];
    float4 v1 = base[(size_t)(r0 + 1) * (WW / 4)];
    float4 v2 = base[(size_t)(r0 + 2) * (WW / 4)];
    float4 v3 = base[(size_t)(r0 + 3) * (WW / 4)];

    unsigned pk = 0;          // hi<<16 | lo
    int rmin_t = 255;
    int rmax_t = 0;
    unsigned cm4 = 0;

#define PROC(v, r)                                                             \
    {                                                                          \
        float mn = fminf(fminf(v.x, v.y), fminf(v.z, v.w));                    \
        float mx = fmaxf(fmaxf(v.x, v.y), fmaxf(v.z, v.w));                    \
        if (mx > -1.f) {                                                       \
            if (mn > 1.f) {                                                    \
                pk += 0x00040004u;                                             \
                rmin_t = min(rmin_t, r);                                       \
                rmax_t = r;                                                    \
                cm4 |= 0xFu;                                                   \
            } else {                                                           \
                int h = (v.x > 1.f) + (v.y > 1.f) + (v.z > 1.f) + (v.w > 1.f); \
                int l = (v.x > -1.f) + (v.y > -1.f) + (v.z > -1.f) +           \
                        (v.w > -1.f);                                          \
                pk += ((unsigned)h << 16) + (unsigned)l;                       \
                unsigned m = (v.x > 0.f) | ((v.y > 0.f) << 1) |                \
                             ((v.z > 0.f) << 2) | ((v.w > 0.f) << 3);          \
                if (m) {                                                       \
                    rmin_t = min(rmin_t, r);                                   \
                    rmax_t = r;                                                \
                    cm4 |= m;                                                  \
                }                                                              \
            }                                                                  \
        }                                                                      \
    }

    PROC(v0, r0 + 0)
    PROC(v1, r0 + 1)
    PROC(v2, r0 + 2)
    PROC(v3, r0 + 3)
#undef PROC

    // Pack bbox into byte-min-reducible word (255 = neutral per byte).
    unsigned p;
    if (cm4) {
        int cmin_t = col0 + (__ffs(cm4) - 1);
        int cmax_t = col0 + (31 - __clz(cm4));
        p = ((unsigned)rmin_t << 24) | ((unsigned)(255 - rmax_t) << 16) |
            ((unsigned)cmin_t << 8) | (unsigned)(255 - cmax_t);
    } else {
        p = 0xFFFFFFFFu;   // empty (genuine boxes can never be all-0xFF)
    }

    // warp reduce: byte-wise min for bbox, packed add for counts
#pragma unroll
    for (int o = 16; o > 0; o >>= 1) {
        p  = __vminu4(p, __shfl_down_sync(0xffffffffu, p, o));
        pk += __shfl_down_sync(0xffffffffu, pk, o);
    }

    __shared__ unsigned s_p[8], s_pk[8];
    const int warp = tid >> 5;
    if ((tid & 31) == 0) { s_p[warp] = p; s_pk[warp] = pk; }
    __syncthreads();
    if (tid == 0) {
        unsigned P = s_p[0], K = s_pk[0];
#pragma unroll
        for (int w = 1; w < 8; w++) { P = __vminu4(P, s_p[w]); K += s_pk[w]; }
        const int idx = q * NM + n;
        g_pp[idx] = P;
        g_pk[idx] = K;
    }
}

// ---------------------------------------------------------------------------
// Kernel B: single block (1024 threads). Merge partials, build boxes+validity,
// compact valid candidates, bitonic-sort next-pow2(V), NMS via suppression
// bitmasks (V<=256) or iterative fallback.
// ---------------------------------------------------------------------------
__global__ void __launch_bounds__(1024) nms_kernel(const float* __restrict__ iou,
                                                   float* __restrict__ out_keep,
                                                   float* __restrict__ out_boxes,
                                                   int write_extra) {
    __shared__ float4 s_bx[NM];                // boxes in ORIGINAL index order
    __shared__ float  s_sc[NM];                // compacted+sorted scores
    __shared__ int    s_ord[NM];               // compacted+sorted original idx
    __shared__ float  s_area[NM];              // area per sorted candidate
    __shared__ unsigned s_sup[256 * 8];        // suppression bitmask rows (V<=256)
    __shared__ unsigned s_live[8];
    __shared__ unsigned char s_keep[NM];       // keep flags (sorted order)
    __shared__ int s_cnt;

    const int tid = threadIdx.x;

    // ---- merge NQ partials ----
    unsigned P = 0xFFFFFFFFu, K = 0;
#pragma unroll
    for (int q = 0; q < NQ; q++) {
        const int idx = q * NM + tid;
        P = __vminu4(P, g_pp[idx]);
        K += g_pk[idx];
    }
    const int hi = (int)(K >> 16);
    const int lo = (int)(K & 0xFFFFu);

    float4 box;
    if (P == 0xFFFFFFFFu) {
        box = make_float4(0.f, 0.f, 0.f, 0.f);  // empty mask -> zeros
    } else {
        box = make_float4((float)((P >> 8) & 0xFF),          // left  = cmin
                          (float)(P >> 24),                  // top   = rmin
                          (float)(255 - (P & 0xFF)),         // right = cmax
                          (float)(255 - ((P >> 16) & 0xFF)));// bottom= rmax
    }
    s_bx[tid] = box;

    const float ip   = iou[tid];
    const float stab = (float)hi / fmaxf((float)lo, 1.0f);
    const bool  valid = (ip > 0.88f) && (stab >= 0.95f);

    if (tid == 0) s_cnt = 0;
    __syncthreads();
    int pos = -1;
    if (valid) pos = atomicAdd(&s_cnt, 1);
    __syncthreads();
    const int V = s_cnt;

    if (pos >= 0) { s_sc[pos] = ip; s_ord[pos] = tid; }

    int Npad = 1;
    while (Npad < V) Npad <<= 1;
    if (Npad < 2) Npad = 2;
    if (tid >= V && tid < Npad) { s_sc[tid] = -CUDART_INF_F; s_ord[tid] = NM; }
    __syncthreads();

    if (V > 0) {
        // ---- bitonic sort over Npad entries (desc score, asc idx tie-break) ----
        for (int k = 2; k <= Npad; k <<= 1) {
            for (int j = k >> 1; j > 0; j >>= 1) {
                if (tid < Npad) {
                    const int ixj = tid ^ j;
                    if (ixj > tid) {
                        float sa = s_sc[tid], sb = s_sc[ixj];
                        int   ia = s_ord[tid], ib = s_ord[ixj];
                        bool dir = ((tid & k) == 0);  // descending segment
                        bool aBb = (sa > sb) || (sa == sb && ia < ib);
                        bool bBa = (sb > sa) || (sb == sa && ib < ia);
                        if (dir ? bBa : aBb) {
                            s_sc[tid] = sb; s_sc[ixj] = sa;
                            s_ord[tid] = ib; s_ord[ixj] = ia;
                        }
                    }
                }
                __syncthreads();
            }
        }

        if (tid < V) {
            float4 b = s_bx[s_ord[tid]];
            s_area[tid] = fmaxf(b.z - b.x, 0.f) * fmaxf(b.w - b.y, 0.f);
        }
        __syncthreads();

        if (V <= 256) {
            // ---- parallel suppression-matrix build ----
            if (tid < V) {
                const float4 bi = s_bx[s_ord[tid]];
                const float  ai = s_area[tid];
                unsigned w[8] = {0, 0, 0, 0, 0, 0, 0, 0};
                for (int j = tid + 1; j < V; j++) {
                    const float4 bj = s_bx[s_ord[j]];
                    float x0 = fmaxf(bi.x, bj.x), y0 = fmaxf(bi.y, bj.y);
                    float x1 = fminf(bi.z, bj.z), y1 = fminf(bi.w, bj.w);
                    float inter = fmaxf(x1 - x0, 0.f) * fmaxf(y1 - y0, 0.f);
                    float v = inter / fmaxf(ai + s_area[j] - inter, 1e-6f);
                    if (v > 0.7f) w[j >> 5] |= 1u << (j & 31);
                }
#pragma unroll
                for (int k = 0; k < 8; k++) s_sup[tid * 8 + k] = w[k];
            }
            __syncthreads();

            // ---- serial greedy resolution over bitmasks ----
            if (tid == 0) {
                unsigned live[8];
#pragma unroll
                for (int k = 0; k < 8; k++) {
                    int rem = V - k * 32;
                    live[k] = (rem >= 32) ? 0xffffffffu
                                          : (rem > 0 ? ((1u << rem) - 1u) : 0u);
                }
                for (int i = 0; i < V; i++) {
                    if ((live[i >> 5] >> (i & 31)) & 1u) {
#pragma unroll
                        for (int k = 0; k < 8; k++) live[k] &= ~s_sup[i * 8 + k];
                    }
                }
#pragma unroll
                for (int k = 0; k < 8; k++) s_live[k] = live[k];
            }
            __syncthreads();
            if (tid < V)
                s_keep[tid] = (s_live[tid >> 5] >> (tid & 31)) & 1u;
        } else {
            // ---- fallback: iterative greedy (rare) ----
            if (tid < Npad) s_keep[tid] = (tid < V) ? 1 : 0;
            __syncthreads();
            float4 mb = make_float4(0, 0, 0, 0);
            float  ma = 0.f;
            if (tid < V) { mb = s_bx[s_ord[tid]]; ma = s_area[tid]; }
            for (int i = 0; i < V; i++) {
                if (tid < V && s_keep[i] && tid > i && s_keep[tid]) {
                    float4 pb = s_bx[s_ord[i]];
                    float x0 = fmaxf(pb.x, mb.x), y0 = fmaxf(pb.y, mb.y);
                    float x1 = fminf(pb.z, mb.z), y1 = fminf(pb.w, mb.w);
                    float inter = fmaxf(x1 - x0, 0.f) * fmaxf(y1 - y0, 0.f);
                    float v = inter / fmaxf(s_area[i] + ma - inter, 1e-6f);
                    if (v > 0.7f) s_keep[tid] = 0;
                }
                __syncthreads();
            }
        }
    }

    // ---- outputs: defaults, then kept overrides (ordered by __syncthreads) ----
    g_gated[tid] = 0.f;
    if (write_extra) {
        out_keep[tid] = 0.f;
        reinterpret_cast<float4*>(out_boxes)[tid] = s_bx[tid];
    }
    __syncthreads();
    if (tid < V && s_keep[tid]) {
        const int oi = s_ord[tid];
        g_gated[oi] = s_sc[tid];
        if (write_extra) out_keep[oi] = 1.f;
    }
}

// ---------------------------------------------------------------------------
// Kernel C: out = sigmoid(logits) * gated[n]. Zero-gated blocks stream zeros.
// grid = (16, NM), 256 threads, 4 coalesced float4 per thread.
// ---------------------------------------------------------------------------
__global__ void __launch_bounds__(256) out_kernel(const float* __restrict__ logits,
                                                  float* __restrict__ out) {
    const int n   = blockIdx.y;
    const int tid = threadIdx.x;
    const size_t base = (size_t)n * HW + (size_t)blockIdx.x * 4096;
    const float4* __restrict__ in4 = reinterpret_cast<const float4*>(logits + base);
    float4* __restrict__ o4 = reinterpret_cast<float4*>(out + base);

    const float g = g_gated[n];
    if (g == 0.f) {
        const float4 z = make_float4(0.f, 0.f, 0.f, 0.f);
#pragma unroll
        for (int k = 0; k < 4; k++) o4[k * 256 + tid] = z;
    } else {
#pragma unroll
        for (int k = 0; k < 4; k++) {
            float4 v = in4[k * 256 + tid];
            float4 r;
            r.x = g / (1.f + __expf(-v.x));
            r.y = g / (1.f + __expf(-v.y));
            r.z = g / (1.f + __expf(-v.z));
            r.w = g / (1.f + __expf(-v.w));
            o4[k * 256 + tid] = r;
        }
    }
}

// ---------------------------------------------------------------------------
extern "C" void kernel_launch(void* const* d_in, const int* in_sizes, int n_in,
                              void* d_out, int out_size) {
    const float* logits = (const float*)d_in[0];
    const float* iou    = (const float*)d_in[1];
    if (n_in >= 2 && in_sizes[0] == NM && in_sizes[1] == NM * HW) {
        logits = (const float*)d_in[1];
        iou    = (const float*)d_in[0];
    }

    float* out = (float*)d_out;
    const long long NHW = (long long)NM * HW;
    int write_extra = (out_size >= NHW + NM + NM * 4) ? 1 : 0;
    float* out_keep  = out + NHW;
    float* out_boxes = out + NHW + NM;

    stats_kernel<<<dim3(NM, NQ), 256>>>(logits);
    nms_kernel<<<1, 1024>>>(iou, out_keep, out_boxes, write_extra);
    out_kernel<<<dim3(16, NM), 256>>>(logits, out);
}